// round 8
// baseline (speedup 1.0000x reference)
#include <cuda_runtime.h>
#include <cuda_bf16.h>
#include <math.h>
#include <stdint.h>

// Problem constants
#define NN     20000
#define EE     400000
#define ETOT   420000
#define INC    768
#define HID    128
#define HEADS  4
#define FMAX   512

// ---------------- device scratch ----------------
__device__ float g_hlin[(size_t)NN * FMAX];
__device__ float g_asrc[(size_t)NN * HEADS];
__device__ float g_adst[(size_t)NN * HEADS];
__device__ __nv_bfloat16 g_ah [(size_t)NN * INC];
__device__ __nv_bfloat16 g_al [(size_t)NN * INC];
__device__ __nv_bfloat16 g_wth[(size_t)FMAX * INC];
__device__ __nv_bfloat16 g_wtl[(size_t)FMAX * INC];
// CSR (built once per launch)
__device__ int g_deg[NN];
__device__ int g_cur[NN];
__device__ int g_rowptr[NN + 1];
__device__ int g_eperm[ETOT];

// ---------------- misc helpers ----------------
__device__ __forceinline__ int clampN(int v) { return v < 0 ? 0 : (v >= NN ? NN - 1 : v); }
__device__ __forceinline__ uint32_t smem_u32(const void* p) {
    uint32_t a;
    asm("{ .reg .u64 t; cvta.to.shared.u64 t, %1; cvt.u32.u64 %0, t; }" : "=r"(a) : "l"(p));
    return a;
}

__global__ void zero_int2_kernel(int* __restrict__ a, int* __restrict__ b, int n) {
    int i = blockIdx.x * blockDim.x + threadIdx.x;
    if (i < n) { a[i] = 0; b[i] = 0; }
}

// ---------------- CSR build ----------------
__global__ void count_kernel(const int* __restrict__ ei, int* __restrict__ deg) {
    int e = blockIdx.x * blockDim.x + threadIdx.x;
    if (e >= ETOT) return;
    int d = (e < EE) ? clampN(ei[EE + e]) : e - EE;
    atomicAdd(&deg[d], 1);
}

#define SCAN_T 1024
#define SCAN_CH 20
__global__ void scan_kernel(const int* __restrict__ deg, int* __restrict__ rowptr) {
    __shared__ int sums[SCAN_T];
    int t = threadIdx.x;
    int base = t * SCAN_CH;
    int local = 0;
#pragma unroll
    for (int i = 0; i < SCAN_CH; i++) {
        int idx = base + i;
        if (idx < NN) local += deg[idx];
    }
    sums[t] = local;
    __syncthreads();
    for (int off = 1; off < SCAN_T; off <<= 1) {
        int v = (t >= off) ? sums[t - off] : 0;
        __syncthreads();
        sums[t] += v;
        __syncthreads();
    }
    int run = sums[t] - local;
#pragma unroll
    for (int i = 0; i < SCAN_CH; i++) {
        int idx = base + i;
        if (idx < NN) { rowptr[idx] = run; run += deg[idx]; }
    }
    if (t == SCAN_T - 1) rowptr[NN] = sums[SCAN_T - 1];
}

__global__ void scatter_kernel(const int* __restrict__ ei,
                               const int* __restrict__ rowptr,
                               int* __restrict__ cur, int* __restrict__ eperm) {
    int e = blockIdx.x * blockDim.x + threadIdx.x;
    if (e >= ETOT) return;
    int d = (e < EE) ? clampN(ei[EE + e]) : e - EE;
    int pos = rowptr[d] + atomicAdd(&cur[d], 1);
    eperm[pos] = e;
}

// ---------------- fp32 -> bf16 hi/lo split ----------------
__global__ void split_kernel(const float* __restrict__ x,
                             __nv_bfloat16* __restrict__ hi,
                             __nv_bfloat16* __restrict__ lo, int n) {
    int i = blockIdx.x * blockDim.x + threadIdx.x;
    if (i >= n) return;
    float v = x[i];
    __nv_bfloat16 h = __float2bfloat16(v);
    hi[i] = h;
    lo[i] = __float2bfloat16(v - __bfloat162float(h));
}

// W [K,N] fp32 -> Wt hi/lo [N,K] bf16 (transposed)
__global__ void splitT_kernel(const float* __restrict__ W,
                              __nv_bfloat16* __restrict__ hi,
                              __nv_bfloat16* __restrict__ lo, int K, int Nn) {
    int i = blockIdx.x * blockDim.x + threadIdx.x;
    if (i >= K * Nn) return;
    int k = i / Nn, n = i - k * Nn;
    float v = W[i];
    __nv_bfloat16 h = __float2bfloat16(v);
    size_t o = (size_t)n * K + k;
    hi[o] = h;
    lo[o] = __float2bfloat16(v - __bfloat162float(h));
}

// ---------------- HMMA bf16 GEMM: 3-stage cp.async + ldmatrix ----------------
// C[M,N] = A[M,K] @ B^T (B stored [N,K]); 3-product split Ah*Bh + Ah*Bl + Al*Bh.
// BM=BN=128, BK=16, 8 warps (2x4), warp tile 64x32, single __syncthreads per chunk.
#define SPAD 24
#define TILE_ELEMS (128 * SPAD)
#define STAGE_ELEMS (4 * TILE_ELEMS)
#define GEMM_SMEM (3 * STAGE_ELEMS * 2)   // 73728 bytes

__device__ __forceinline__ void mma_bf16(float* c, const uint32_t* a, const uint32_t* b) {
    asm volatile("mma.sync.aligned.m16n8k16.row.col.f32.bf16.bf16.f32 "
                 "{%0,%1,%2,%3}, {%4,%5,%6,%7}, {%8,%9}, {%0,%1,%2,%3};"
                 : "+f"(c[0]), "+f"(c[1]), "+f"(c[2]), "+f"(c[3])
                 : "r"(a[0]), "r"(a[1]), "r"(a[2]), "r"(a[3]),
                   "r"(b[0]), "r"(b[1]));
}
#define LDM_X4(r0, r1, r2, r3, a) \
    asm volatile("ldmatrix.sync.aligned.m8n8.x4.shared.b16 {%0,%1,%2,%3}, [%4];" \
                 : "=r"(r0), "=r"(r1), "=r"(r2), "=r"(r3) : "r"(a))
#define CP_ASYNC16(dst, src) \
    asm volatile("cp.async.ca.shared.global [%0], [%1], 16;" :: "r"(dst), "l"(src))

__global__ void __launch_bounds__(256)
hgemm_kernel(const __nv_bfloat16* __restrict__ Ah,
             const __nv_bfloat16* __restrict__ Al,
             const __nv_bfloat16* __restrict__ Bh,
             const __nv_bfloat16* __restrict__ Bl,
             float* __restrict__ C, int M, int K, int Nn) {
    extern __shared__ __nv_bfloat16 sm[];   // 3 stages x 4 tiles x TILE_ELEMS

    const int tid  = threadIdx.x;
    const int lane = tid & 31;
    const int wid  = tid >> 5;
    const int wm   = (wid >> 2) * 64;
    const int wn   = (wid & 3) * 32;
    const int row0 = blockIdx.y * 128;
    const int col0 = blockIdx.x * 128;
    const int g4   = lane >> 2;
    const int t4   = lane & 3;

    const int a_off = (lane & 15) * SPAD + (lane >> 4) * 8;
    const int b_off = ((lane & 7) + ((lane & 16) ? 8 : 0)) * SPAD + ((lane & 8) ? 8 : 0);

    const int lr = tid >> 1;
    const int lc = (tid & 1) * 8;

    float acc[4][4][4];
#pragma unroll
    for (int a = 0; a < 4; a++)
#pragma unroll
        for (int b = 0; b < 4; b++)
#pragma unroll
            for (int c = 0; c < 4; c++) acc[a][b][c] = 0.f;

    const int nCh = K >> 4;
    const int gra = min(row0 + lr, M - 1);
    const int grb = col0 + lr;
    const uint32_t smb = smem_u32(sm);

#define ISSUE(ch, st) do {                                                      \
    uint32_t sb_ = smb + (uint32_t)(st) * (STAGE_ELEMS * 2);                    \
    int kc0_ = (ch) << 4;                                                       \
    uint32_t d_ = sb_ + (uint32_t)(lr * SPAD + lc) * 2;                         \
    CP_ASYNC16(d_ + 0 * TILE_ELEMS * 2, Ah + (size_t)gra * K + kc0_ + lc);      \
    CP_ASYNC16(d_ + 1 * TILE_ELEMS * 2, Al + (size_t)gra * K + kc0_ + lc);      \
    CP_ASYNC16(d_ + 2 * TILE_ELEMS * 2, Bh + (size_t)grb * K + kc0_ + lc);      \
    CP_ASYNC16(d_ + 3 * TILE_ELEMS * 2, Bl + (size_t)grb * K + kc0_ + lc);      \
    asm volatile("cp.async.commit_group;");                                     \
} while (0)

    ISSUE(0, 0);
    ISSUE(1, 1);

    int st = 0;       // stage of chunk ch
    for (int ch = 0; ch < nCh; ch++) {
        if (ch == nCh - 1) asm volatile("cp.async.wait_group 0;");
        else               asm volatile("cp.async.wait_group 1;");
        __syncthreads();

        // issue chunk ch+2 into the stage freed by chunk ch-1
        if (ch + 2 < nCh) {
            int st2 = st + 2; if (st2 >= 3) st2 -= 3;
            ISSUE(ch + 2, st2);
        }

        const uint32_t bAh = smb + (uint32_t)st * (STAGE_ELEMS * 2);
        const uint32_t bAl = bAh + TILE_ELEMS * 2;
        const uint32_t bBh = bAl + TILE_ELEMS * 2;
        const uint32_t bBl = bBh + TILE_ELEMS * 2;

        uint32_t bh[4][2], bl[4][2];
#pragma unroll
        for (int ntp = 0; ntp < 2; ntp++) {
            uint32_t off = (uint32_t)((wn + ntp * 16) * SPAD + b_off) * 2;
            LDM_X4(bh[2 * ntp][0], bh[2 * ntp][1], bh[2 * ntp + 1][0], bh[2 * ntp + 1][1], bBh + off);
            LDM_X4(bl[2 * ntp][0], bl[2 * ntp][1], bl[2 * ntp + 1][0], bl[2 * ntp + 1][1], bBl + off);
        }
#pragma unroll
        for (int mt = 0; mt < 4; mt++) {
            uint32_t off = (uint32_t)((wm + mt * 16) * SPAD + a_off) * 2;
            uint32_t ah[4], al[4];
            LDM_X4(ah[0], ah[1], ah[2], ah[3], bAh + off);
            LDM_X4(al[0], al[1], al[2], al[3], bAl + off);
#pragma unroll
            for (int nt = 0; nt < 4; nt++) {
                mma_bf16(acc[mt][nt], ah, bh[nt]);
                mma_bf16(acc[mt][nt], ah, bl[nt]);
                mma_bf16(acc[mt][nt], al, bh[nt]);
            }
        }
        st++; if (st >= 3) st = 0;
    }
#undef ISSUE

#pragma unroll
    for (int mt = 0; mt < 4; mt++) {
#pragma unroll
        for (int nt = 0; nt < 4; nt++) {
            int gm = row0 + wm + mt * 16 + g4;
            int gc = col0 + wn + nt * 8 + t4 * 2;
            if (gm < M)
                *(float2*)&C[(size_t)gm * Nn + gc] = make_float2(acc[mt][nt][0], acc[mt][nt][1]);
            if (gm + 8 < M)
                *(float2*)&C[(size_t)(gm + 8) * Nn + gc] = make_float2(acc[mt][nt][2], acc[mt][nt][3]);
        }
    }
}

// ---------------- alpha: per (node, head) warp dot products ----------------
template <int H>
__global__ void alpha_kernel(const float* __restrict__ hlin,
                             const float* __restrict__ a_src,
                             const float* __restrict__ a_dst,
                             float* __restrict__ asrc,
                             float* __restrict__ adst) {
    int gw = (blockIdx.x * blockDim.x + threadIdx.x) >> 5;
    int lane = threadIdx.x & 31;
    if (gw >= NN * H) return;
    int n = gw / H, h = gw - n * H;
    const float* hp = hlin + ((size_t)n * H + h) * HID;
    const float* as = a_src + h * HID;
    const float* ad = a_dst + h * HID;
    float ss = 0.f, sd = 0.f;
#pragma unroll
    for (int i = 0; i < HID / 32; i++) {
        float v = hp[lane + i * 32];
        ss = fmaf(v, as[lane + i * 32], ss);
        sd = fmaf(v, ad[lane + i * 32], sd);
    }
#pragma unroll
    for (int o = 16; o; o >>= 1) {
        ss += __shfl_xor_sync(0xffffffffu, ss, o);
        sd += __shfl_xor_sync(0xffffffffu, sd, o);
    }
    if (lane == 0) { asrc[gw] = ss; adst[gw] = sd; }
}

// ---------------- fused aggregate: softmax + weighted gather + finalize ----
template <int H, int MODE>
__global__ void aggregate_kernel(const int* __restrict__ ei,
                                 const int* __restrict__ rowptr,
                                 const int* __restrict__ eperm,
                                 const float* __restrict__ asrc,
                                 const float* __restrict__ adst,
                                 const float* __restrict__ hlin,
                                 const float* __restrict__ bias,
                                 __nv_bfloat16* __restrict__ hi,
                                 __nv_bfloat16* __restrict__ lo,
                                 float* __restrict__ out) {
    int gw = (blockIdx.x * blockDim.x + threadIdx.x) >> 5;
    int lane = threadIdx.x & 31;
    if (gw >= NN * H) return;
    int n = gw / H, h = gw - n * H;
    float adst_nh = adst[gw];
    int beg = rowptr[n], end = rowptr[n + 1];

    float4 acc = make_float4(0.f, 0.f, 0.f, 0.f);
    float ssum = 0.f;

    for (int base = beg; base < end; base += 32) {
        int j = base + lane;
        float vj = 0.f;
        int sj = 0;
        if (j < end) {
            int e = eperm[j];
            sj = (e < EE) ? clampN(ei[e]) : e - EE;
            float v = asrc[(size_t)sj * H + h] + adst_nh;
            v = (v > 0.f) ? v : 0.2f * v;
            vj = __expf(v);
        }
        int cnt = min(32, end - base);
        for (int t = 0; t < cnt; t++) {
            float v = __shfl_sync(0xffffffffu, vj, t);
            int s   = __shfl_sync(0xffffffffu, sj, t);
            const float4* hp = (const float4*)(hlin + ((size_t)s * H + h) * HID);
            float4 hv = hp[lane];
            acc.x = fmaf(v, hv.x, acc.x);
            acc.y = fmaf(v, hv.y, acc.y);
            acc.z = fmaf(v, hv.z, acc.z);
            acc.w = fmaf(v, hv.w, acc.w);
            ssum += v;
        }
    }
    float inv = 1.f / (ssum + 1e-16f);
    int f = h * HID + lane * 4;
    float4 bv = *(const float4*)(bias + f);
    float4 o;
    o.x = acc.x * inv + bv.x;
    o.y = acc.y * inv + bv.y;
    o.z = acc.z * inv + bv.z;
    o.w = acc.w * inv + bv.w;
    if (MODE == 0) {
        o.x = (o.x > 0.f) ? o.x : expm1f(o.x);
        o.y = (o.y > 0.f) ? o.y : expm1f(o.y);
        o.z = (o.z > 0.f) ? o.z : expm1f(o.z);
        o.w = (o.w > 0.f) ? o.w : expm1f(o.w);
        size_t off = (size_t)gw * HID + lane * 4;
        __nv_bfloat16 hx = __float2bfloat16(o.x);
        __nv_bfloat16 hy = __float2bfloat16(o.y);
        __nv_bfloat16 hz = __float2bfloat16(o.z);
        __nv_bfloat16 hw = __float2bfloat16(o.w);
        hi[off + 0] = hx;  lo[off + 0] = __float2bfloat16(o.x - __bfloat162float(hx));
        hi[off + 1] = hy;  lo[off + 1] = __float2bfloat16(o.y - __bfloat162float(hy));
        hi[off + 2] = hz;  lo[off + 2] = __float2bfloat16(o.z - __bfloat162float(hz));
        hi[off + 3] = hw;  lo[off + 3] = __float2bfloat16(o.w - __bfloat162float(hw));
    } else {
        *(float4*)&out[(size_t)n * HID + lane * 4] = o;
    }
}

// ---------------- host orchestration ----------------
struct Buffers {
    float *hlin, *asrc, *adst;
    __nv_bfloat16 *ah, *al, *wth, *wtl;
    int *deg, *cur, *rowptr, *eperm;
};

template <int H, int MODE>
static void run_layer(int K, const float* W, const float* a_src, const float* a_dst,
                      const float* bias, const Buffers& B, const int* ei, float* out_fp32) {
    const int F = H * HID;
    {
        int nw = K * F;
        splitT_kernel<<<(nw + 255) / 256, 256>>>(W, B.wth, B.wtl, K, F);
    }
    {
        dim3 grid(F / 128, (NN + 127) / 128);
        hgemm_kernel<<<grid, 256, GEMM_SMEM>>>(B.ah, B.al, B.wth, B.wtl, B.hlin, NN, K, F);
    }
    {
        int warps = NN * H;
        alpha_kernel<H><<<(warps * 32 + 255) / 256, 256>>>(B.hlin, a_src, a_dst, B.asrc, B.adst);
    }
    {
        int warps = NN * H;
        aggregate_kernel<H, MODE><<<(warps * 32 + 255) / 256, 256>>>(
            ei, B.rowptr, B.eperm, B.asrc, B.adst, B.hlin, bias, B.ah, B.al, out_fp32);
    }
}

extern "C" void kernel_launch(void* const* d_in, const int* in_sizes, int n_in,
                              void* d_out, int out_size) {
    const float* x       = (const float*)d_in[0];
    const int*   ei      = (const int*)d_in[1];
    const float* W1      = (const float*)d_in[2];
    const float* a1_src  = (const float*)d_in[3];
    const float* a1_dst  = (const float*)d_in[4];
    const float* b1      = (const float*)d_in[5];
    const float* W2      = (const float*)d_in[6];
    const float* a2_src  = (const float*)d_in[7];
    const float* a2_dst  = (const float*)d_in[8];
    const float* b2      = (const float*)d_in[9];
    const float* W3      = (const float*)d_in[10];
    const float* a3_src  = (const float*)d_in[11];
    const float* a3_dst  = (const float*)d_in[12];
    const float* b3      = (const float*)d_in[13];

    Buffers B;
    cudaGetSymbolAddress((void**)&B.hlin,   g_hlin);
    cudaGetSymbolAddress((void**)&B.asrc,   g_asrc);
    cudaGetSymbolAddress((void**)&B.adst,   g_adst);
    cudaGetSymbolAddress((void**)&B.ah,     g_ah);
    cudaGetSymbolAddress((void**)&B.al,     g_al);
    cudaGetSymbolAddress((void**)&B.wth,    g_wth);
    cudaGetSymbolAddress((void**)&B.wtl,    g_wtl);
    cudaGetSymbolAddress((void**)&B.deg,    g_deg);
    cudaGetSymbolAddress((void**)&B.cur,    g_cur);
    cudaGetSymbolAddress((void**)&B.rowptr, g_rowptr);
    cudaGetSymbolAddress((void**)&B.eperm,  g_eperm);

    cudaFuncSetAttribute(hgemm_kernel, cudaFuncAttributeMaxDynamicSharedMemorySize, GEMM_SMEM);

    // CSR build (once; reused by all 3 layers)
    zero_int2_kernel<<<(NN + 255) / 256, 256>>>(B.deg, B.cur, NN);
    count_kernel<<<(ETOT + 255) / 256, 256>>>(ei, B.deg);
    scan_kernel<<<1, SCAN_T>>>(B.deg, B.rowptr);
    scatter_kernel<<<(ETOT + 255) / 256, 256>>>(ei, B.rowptr, B.cur, B.eperm);

    // split x into bf16 hi/lo (layer-1 GEMM input)
    {
        int na = NN * INC;
        split_kernel<<<(na + 255) / 256, 256>>>(x, B.ah, B.al, na);
    }
    run_layer<HEADS, 0>(INC,  W1, a1_src, a1_dst, b1, B, ei, nullptr);
    run_layer<HEADS, 0>(FMAX, W2, a2_src, a2_dst, b2, B, ei, nullptr);
    run_layer<1, 1>    (FMAX, W3, a3_src, a3_dst, b3, B, ei, (float*)d_out);
}

// round 9
// speedup vs baseline: 1.0439x; 1.0439x over previous
#include <cuda_runtime.h>
#include <cuda_bf16.h>
#include <math.h>
#include <stdint.h>

// Problem constants
#define NN     20000
#define EE     400000
#define ETOT   420000
#define INC    768
#define HID    128
#define HEADS  4
#define FMAX   512

// ---------------- device scratch ----------------
__device__ float g_hlin[(size_t)NN * FMAX];
__device__ float g_asrc[(size_t)NN * HEADS];
__device__ float g_adst[(size_t)NN * HEADS];
__device__ __nv_bfloat16 g_ah [(size_t)NN * INC];
__device__ __nv_bfloat16 g_al [(size_t)NN * INC];
__device__ __nv_bfloat16 g_wth[(size_t)FMAX * INC];
__device__ __nv_bfloat16 g_wtl[(size_t)FMAX * INC];
// CSR (built once per launch); esrc holds SOURCE node ids bucketed by dst
__device__ int g_deg[NN];
__device__ int g_cur[NN];
__device__ int g_rowptr[NN + 1];
__device__ int g_esrc[ETOT];

// ---------------- misc helpers ----------------
__device__ __forceinline__ int clampN(int v) { return v < 0 ? 0 : (v >= NN ? NN - 1 : v); }
__device__ __forceinline__ uint32_t smem_u32(const void* p) {
    uint32_t a;
    asm("{ .reg .u64 t; cvta.to.shared.u64 t, %1; cvt.u32.u64 %0, t; }" : "=r"(a) : "l"(p));
    return a;
}

__global__ void zero_int2_kernel(int* __restrict__ a, int* __restrict__ b, int n) {
    int i = blockIdx.x * blockDim.x + threadIdx.x;
    if (i < n) { a[i] = 0; b[i] = 0; }
}

// ---------------- CSR build ----------------
__global__ void count_kernel(const int* __restrict__ ei, int* __restrict__ deg) {
    int e = blockIdx.x * blockDim.x + threadIdx.x;
    if (e >= ETOT) return;
    int d = (e < EE) ? clampN(ei[EE + e]) : e - EE;
    atomicAdd(&deg[d], 1);
}

#define SCAN_T 1024
#define SCAN_CH 20
__global__ void scan_kernel(const int* __restrict__ deg, int* __restrict__ rowptr) {
    __shared__ int sums[SCAN_T];
    int t = threadIdx.x;
    int base = t * SCAN_CH;
    int local = 0;
#pragma unroll
    for (int i = 0; i < SCAN_CH; i++) {
        int idx = base + i;
        if (idx < NN) local += deg[idx];
    }
    sums[t] = local;
    __syncthreads();
    for (int off = 1; off < SCAN_T; off <<= 1) {
        int v = (t >= off) ? sums[t - off] : 0;
        __syncthreads();
        sums[t] += v;
        __syncthreads();
    }
    int run = sums[t] - local;
#pragma unroll
    for (int i = 0; i < SCAN_CH; i++) {
        int idx = base + i;
        if (idx < NN) { rowptr[idx] = run; run += deg[idx]; }
    }
    if (t == SCAN_T - 1) rowptr[NN] = sums[SCAN_T - 1];
}

// store the SOURCE node id directly (saves one indirection in aggregate)
__global__ void scatter_kernel(const int* __restrict__ ei,
                               const int* __restrict__ rowptr,
                               int* __restrict__ cur, int* __restrict__ esrc) {
    int e = blockIdx.x * blockDim.x + threadIdx.x;
    if (e >= ETOT) return;
    int s, d;
    if (e < EE) { s = clampN(ei[e]); d = clampN(ei[EE + e]); } else { s = d = e - EE; }
    int pos = rowptr[d] + atomicAdd(&cur[d], 1);
    esrc[pos] = s;
}

// ---------------- fp32 -> bf16 hi/lo split ----------------
__global__ void split_kernel(const float* __restrict__ x,
                             __nv_bfloat16* __restrict__ hi,
                             __nv_bfloat16* __restrict__ lo, int n) {
    int i = blockIdx.x * blockDim.x + threadIdx.x;
    if (i >= n) return;
    float v = x[i];
    __nv_bfloat16 h = __float2bfloat16(v);
    hi[i] = h;
    lo[i] = __float2bfloat16(v - __bfloat162float(h));
}

// W [K,N] fp32 -> Wt hi/lo [N,K] bf16 (transposed)
__global__ void splitT_kernel(const float* __restrict__ W,
                              __nv_bfloat16* __restrict__ hi,
                              __nv_bfloat16* __restrict__ lo, int K, int Nn) {
    int i = blockIdx.x * blockDim.x + threadIdx.x;
    if (i >= K * Nn) return;
    int k = i / Nn, n = i - k * Nn;
    float v = W[i];
    __nv_bfloat16 h = __float2bfloat16(v);
    size_t o = (size_t)n * K + k;
    hi[o] = h;
    lo[o] = __float2bfloat16(v - __bfloat162float(h));
}

// ---------------- HMMA bf16 GEMM: 2-stage cp.async + ldmatrix (R7 proven) ----
#define SPAD 24
#define TILE_ELEMS (128 * SPAD)

__device__ __forceinline__ void mma_bf16(float* c, const uint32_t* a, const uint32_t* b) {
    asm volatile("mma.sync.aligned.m16n8k16.row.col.f32.bf16.bf16.f32 "
                 "{%0,%1,%2,%3}, {%4,%5,%6,%7}, {%8,%9}, {%0,%1,%2,%3};"
                 : "+f"(c[0]), "+f"(c[1]), "+f"(c[2]), "+f"(c[3])
                 : "r"(a[0]), "r"(a[1]), "r"(a[2]), "r"(a[3]),
                   "r"(b[0]), "r"(b[1]));
}
#define LDM_X4(r0, r1, r2, r3, a) \
    asm volatile("ldmatrix.sync.aligned.m8n8.x4.shared.b16 {%0,%1,%2,%3}, [%4];" \
                 : "=r"(r0), "=r"(r1), "=r"(r2), "=r"(r3) : "r"(a))
#define CP_ASYNC16(dst, src) \
    asm volatile("cp.async.ca.shared.global [%0], [%1], 16;" :: "r"(dst), "l"(src))

__global__ void __launch_bounds__(256)
hgemm_kernel(const __nv_bfloat16* __restrict__ Ah,
             const __nv_bfloat16* __restrict__ Al,
             const __nv_bfloat16* __restrict__ Bh,
             const __nv_bfloat16* __restrict__ Bl,
             float* __restrict__ C, int M, int K, int Nn) {
    __shared__ __nv_bfloat16 sm[2 * 4 * TILE_ELEMS];   // 48KB

    const int tid  = threadIdx.x;
    const int lane = tid & 31;
    const int wid  = tid >> 5;
    const int wm   = (wid >> 2) * 64;
    const int wn   = (wid & 3) * 32;
    const int row0 = blockIdx.y * 128;
    const int col0 = blockIdx.x * 128;
    const int g4   = lane >> 2;
    const int t4   = lane & 3;

    const int a_off = (lane & 15) * SPAD + (lane >> 4) * 8;
    const int b_off = ((lane & 7) + ((lane & 16) ? 8 : 0)) * SPAD + ((lane & 8) ? 8 : 0);

    const int lr = tid >> 1;
    const int lc = (tid & 1) * 8;

    float acc[4][4][4];
#pragma unroll
    for (int a = 0; a < 4; a++)
#pragma unroll
        for (int b = 0; b < 4; b++)
#pragma unroll
            for (int c = 0; c < 4; c++) acc[a][b][c] = 0.f;

    const int nCh = K >> 4;
    const int gra = min(row0 + lr, M - 1);
    const int grb = col0 + lr;

#define ISSUE(ch) do {                                                          \
    __nv_bfloat16* sb_ = sm + ((ch) & 1) * 4 * TILE_ELEMS;                      \
    int kc0_ = (ch) << 4;                                                       \
    uint32_t d0 = smem_u32(sb_ + 0 * TILE_ELEMS + lr * SPAD + lc);              \
    uint32_t d1 = smem_u32(sb_ + 1 * TILE_ELEMS + lr * SPAD + lc);              \
    uint32_t d2 = smem_u32(sb_ + 2 * TILE_ELEMS + lr * SPAD + lc);              \
    uint32_t d3 = smem_u32(sb_ + 3 * TILE_ELEMS + lr * SPAD + lc);              \
    CP_ASYNC16(d0, Ah + (size_t)gra * K + kc0_ + lc);                           \
    CP_ASYNC16(d1, Al + (size_t)gra * K + kc0_ + lc);                           \
    CP_ASYNC16(d2, Bh + (size_t)grb * K + kc0_ + lc);                           \
    CP_ASYNC16(d3, Bl + (size_t)grb * K + kc0_ + lc);                           \
    asm volatile("cp.async.commit_group;");                                     \
} while (0)

    ISSUE(0);
    for (int ch = 0; ch < nCh; ch++) {
        if (ch + 1 < nCh) {
            ISSUE(ch + 1);
            asm volatile("cp.async.wait_group 1;");
        } else {
            asm volatile("cp.async.wait_group 0;");
        }
        __syncthreads();

        const __nv_bfloat16* sb = sm + (ch & 1) * 4 * TILE_ELEMS;
        const uint32_t bAh = smem_u32(sb);
        const uint32_t bAl = bAh + TILE_ELEMS * 2;
        const uint32_t bBh = bAl + TILE_ELEMS * 2;
        const uint32_t bBl = bBh + TILE_ELEMS * 2;

        uint32_t bh[4][2], bl[4][2];
#pragma unroll
        for (int ntp = 0; ntp < 2; ntp++) {
            uint32_t off = (uint32_t)((wn + ntp * 16) * SPAD + b_off) * 2;
            LDM_X4(bh[2 * ntp][0], bh[2 * ntp][1], bh[2 * ntp + 1][0], bh[2 * ntp + 1][1], bBh + off);
            LDM_X4(bl[2 * ntp][0], bl[2 * ntp][1], bl[2 * ntp + 1][0], bl[2 * ntp + 1][1], bBl + off);
        }
#pragma unroll
        for (int mt = 0; mt < 4; mt++) {
            uint32_t off = (uint32_t)((wm + mt * 16) * SPAD + a_off) * 2;
            uint32_t ah[4], al[4];
            LDM_X4(ah[0], ah[1], ah[2], ah[3], bAh + off);
            LDM_X4(al[0], al[1], al[2], al[3], bAl + off);
#pragma unroll
            for (int nt = 0; nt < 4; nt++) {
                mma_bf16(acc[mt][nt], ah, bh[nt]);
                mma_bf16(acc[mt][nt], ah, bl[nt]);
                mma_bf16(acc[mt][nt], al, bh[nt]);
            }
        }
        __syncthreads();
    }
#undef ISSUE

#pragma unroll
    for (int mt = 0; mt < 4; mt++) {
#pragma unroll
        for (int nt = 0; nt < 4; nt++) {
            int gm = row0 + wm + mt * 16 + g4;
            int gc = col0 + wn + nt * 8 + t4 * 2;
            if (gm < M)
                *(float2*)&C[(size_t)gm * Nn + gc] = make_float2(acc[mt][nt][0], acc[mt][nt][1]);
            if (gm + 8 < M)
                *(float2*)&C[(size_t)(gm + 8) * Nn + gc] = make_float2(acc[mt][nt][2], acc[mt][nt][3]);
        }
    }
}

// ---------------- alpha: per (node, head) warp dot products ----------------
template <int H>
__global__ void alpha_kernel(const float* __restrict__ hlin,
                             const float* __restrict__ a_src,
                             const float* __restrict__ a_dst,
                             float* __restrict__ asrc,
                             float* __restrict__ adst) {
    int gw = (blockIdx.x * blockDim.x + threadIdx.x) >> 5;
    int lane = threadIdx.x & 31;
    if (gw >= NN * H) return;
    int n = gw / H, h = gw - n * H;
    const float* hp = hlin + ((size_t)n * H + h) * HID;
    const float* as = a_src + h * HID;
    const float* ad = a_dst + h * HID;
    float ss = 0.f, sd = 0.f;
#pragma unroll
    for (int i = 0; i < HID / 32; i++) {
        float v = hp[lane + i * 32];
        ss = fmaf(v, as[lane + i * 32], ss);
        sd = fmaf(v, ad[lane + i * 32], sd);
    }
#pragma unroll
    for (int o = 16; o; o >>= 1) {
        ss += __shfl_xor_sync(0xffffffffu, ss, o);
        sd += __shfl_xor_sync(0xffffffffu, sd, o);
    }
    if (lane == 0) { asrc[gw] = ss; adst[gw] = sd; }
}

// ---------------- fused aggregate (4x unrolled gather) ----------------------
template <int H, int MODE>
__global__ void aggregate_kernel(const int* __restrict__ rowptr,
                                 const int* __restrict__ esrc,
                                 const float* __restrict__ asrc,
                                 const float* __restrict__ adst,
                                 const float* __restrict__ hlin,
                                 const float* __restrict__ bias,
                                 __nv_bfloat16* __restrict__ hi,
                                 __nv_bfloat16* __restrict__ lo,
                                 float* __restrict__ out) {
    int gw = (blockIdx.x * blockDim.x + threadIdx.x) >> 5;
    int lane = threadIdx.x & 31;
    if (gw >= NN * H) return;
    int n = gw / H, h = gw - n * H;
    float adst_nh = adst[gw];
    int beg = rowptr[n], end = rowptr[n + 1];

    float4 acc = make_float4(0.f, 0.f, 0.f, 0.f);
    float ssum = 0.f;

    for (int base = beg; base < end; base += 32) {
        int j = base + lane;
        float vj = 0.f;
        int sj = 0;
        if (j < end) {
            sj = esrc[j];
            float v = asrc[(size_t)sj * H + h] + adst_nh;
            v = (v > 0.f) ? v : 0.2f * v;
            vj = __expf(v);
        }
        int cnt = min(32, end - base);
        int t = 0;
        for (; t + 4 <= cnt; t += 4) {
            float v0 = __shfl_sync(0xffffffffu, vj, t);
            float v1 = __shfl_sync(0xffffffffu, vj, t + 1);
            float v2 = __shfl_sync(0xffffffffu, vj, t + 2);
            float v3 = __shfl_sync(0xffffffffu, vj, t + 3);
            int s0 = __shfl_sync(0xffffffffu, sj, t);
            int s1 = __shfl_sync(0xffffffffu, sj, t + 1);
            int s2 = __shfl_sync(0xffffffffu, sj, t + 2);
            int s3 = __shfl_sync(0xffffffffu, sj, t + 3);
            float4 h0 = ((const float4*)(hlin + ((size_t)s0 * H + h) * HID))[lane];
            float4 h1 = ((const float4*)(hlin + ((size_t)s1 * H + h) * HID))[lane];
            float4 h2 = ((const float4*)(hlin + ((size_t)s2 * H + h) * HID))[lane];
            float4 h3 = ((const float4*)(hlin + ((size_t)s3 * H + h) * HID))[lane];
            acc.x = fmaf(v0, h0.x, acc.x); acc.y = fmaf(v0, h0.y, acc.y);
            acc.z = fmaf(v0, h0.z, acc.z); acc.w = fmaf(v0, h0.w, acc.w);
            acc.x = fmaf(v1, h1.x, acc.x); acc.y = fmaf(v1, h1.y, acc.y);
            acc.z = fmaf(v1, h1.z, acc.z); acc.w = fmaf(v1, h1.w, acc.w);
            acc.x = fmaf(v2, h2.x, acc.x); acc.y = fmaf(v2, h2.y, acc.y);
            acc.z = fmaf(v2, h2.z, acc.z); acc.w = fmaf(v2, h2.w, acc.w);
            acc.x = fmaf(v3, h3.x, acc.x); acc.y = fmaf(v3, h3.y, acc.y);
            acc.z = fmaf(v3, h3.z, acc.z); acc.w = fmaf(v3, h3.w, acc.w);
            ssum += (v0 + v1) + (v2 + v3);
        }
        for (; t < cnt; t++) {
            float v = __shfl_sync(0xffffffffu, vj, t);
            int s   = __shfl_sync(0xffffffffu, sj, t);
            float4 hv = ((const float4*)(hlin + ((size_t)s * H + h) * HID))[lane];
            acc.x = fmaf(v, hv.x, acc.x);
            acc.y = fmaf(v, hv.y, acc.y);
            acc.z = fmaf(v, hv.z, acc.z);
            acc.w = fmaf(v, hv.w, acc.w);
            ssum += v;
        }
    }
    float inv = 1.f / (ssum + 1e-16f);
    int f = h * HID + lane * 4;
    float4 bv = *(const float4*)(bias + f);
    float4 o;
    o.x = acc.x * inv + bv.x;
    o.y = acc.y * inv + bv.y;
    o.z = acc.z * inv + bv.z;
    o.w = acc.w * inv + bv.w;
    if (MODE == 0) {
        o.x = (o.x > 0.f) ? o.x : expm1f(o.x);
        o.y = (o.y > 0.f) ? o.y : expm1f(o.y);
        o.z = (o.z > 0.f) ? o.z : expm1f(o.z);
        o.w = (o.w > 0.f) ? o.w : expm1f(o.w);
        size_t off = (size_t)gw * HID + lane * 4;
        __nv_bfloat16 hx = __float2bfloat16(o.x);
        __nv_bfloat16 hy = __float2bfloat16(o.y);
        __nv_bfloat16 hz = __float2bfloat16(o.z);
        __nv_bfloat16 hw = __float2bfloat16(o.w);
        hi[off + 0] = hx;  lo[off + 0] = __float2bfloat16(o.x - __bfloat162float(hx));
        hi[off + 1] = hy;  lo[off + 1] = __float2bfloat16(o.y - __bfloat162float(hy));
        hi[off + 2] = hz;  lo[off + 2] = __float2bfloat16(o.z - __bfloat162float(hz));
        hi[off + 3] = hw;  lo[off + 3] = __float2bfloat16(o.w - __bfloat162float(hw));
    } else {
        *(float4*)&out[(size_t)n * HID + lane * 4] = o;
    }
}

// ---------------- host orchestration ----------------
struct Buffers {
    float *hlin, *asrc, *adst;
    __nv_bfloat16 *ah, *al, *wth, *wtl;
    int *deg, *cur, *rowptr, *esrc;
};

template <int H, int MODE>
static void run_layer(int K, const float* W, const float* a_src, const float* a_dst,
                      const float* bias, const Buffers& B, float* out_fp32) {
    const int F = H * HID;
    {
        int nw = K * F;
        splitT_kernel<<<(nw + 255) / 256, 256>>>(W, B.wth, B.wtl, K, F);
    }
    {
        dim3 grid(F / 128, (NN + 127) / 128);
        hgemm_kernel<<<grid, 256>>>(B.ah, B.al, B.wth, B.wtl, B.hlin, NN, K, F);
    }
    {
        int warps = NN * H;
        alpha_kernel<H><<<(warps * 32 + 255) / 256, 256>>>(B.hlin, a_src, a_dst, B.asrc, B.adst);
    }
    {
        int warps = NN * H;
        aggregate_kernel<H, MODE><<<(warps * 32 + 255) / 256, 256>>>(
            B.rowptr, B.esrc, B.asrc, B.adst, B.hlin, bias, B.ah, B.al, out_fp32);
    }
}

extern "C" void kernel_launch(void* const* d_in, const int* in_sizes, int n_in,
                              void* d_out, int out_size) {
    const float* x       = (const float*)d_in[0];
    const int*   ei      = (const int*)d_in[1];
    const float* W1      = (const float*)d_in[2];
    const float* a1_src  = (const float*)d_in[3];
    const float* a1_dst  = (const float*)d_in[4];
    const float* b1      = (const float*)d_in[5];
    const float* W2      = (const float*)d_in[6];
    const float* a2_src  = (const float*)d_in[7];
    const float* a2_dst  = (const float*)d_in[8];
    const float* b2      = (const float*)d_in[9];
    const float* W3      = (const float*)d_in[10];
    const float* a3_src  = (const float*)d_in[11];
    const float* a3_dst  = (const float*)d_in[12];
    const float* b3      = (const float*)d_in[13];

    Buffers B;
    cudaGetSymbolAddress((void**)&B.hlin,   g_hlin);
    cudaGetSymbolAddress((void**)&B.asrc,   g_asrc);
    cudaGetSymbolAddress((void**)&B.adst,   g_adst);
    cudaGetSymbolAddress((void**)&B.ah,     g_ah);
    cudaGetSymbolAddress((void**)&B.al,     g_al);
    cudaGetSymbolAddress((void**)&B.wth,    g_wth);
    cudaGetSymbolAddress((void**)&B.wtl,    g_wtl);
    cudaGetSymbolAddress((void**)&B.deg,    g_deg);
    cudaGetSymbolAddress((void**)&B.cur,    g_cur);
    cudaGetSymbolAddress((void**)&B.rowptr, g_rowptr);
    cudaGetSymbolAddress((void**)&B.esrc,   g_esrc);

    // CSR build (once; reused by all 3 layers)
    zero_int2_kernel<<<(NN + 255) / 256, 256>>>(B.deg, B.cur, NN);
    count_kernel<<<(ETOT + 255) / 256, 256>>>(ei, B.deg);
    scan_kernel<<<1, SCAN_T>>>(B.deg, B.rowptr);
    scatter_kernel<<<(ETOT + 255) / 256, 256>>>(ei, B.rowptr, B.cur, B.esrc);

    // split x into bf16 hi/lo (layer-1 GEMM input)
    {
        int na = NN * INC;
        split_kernel<<<(na + 255) / 256, 256>>>(x, B.ah, B.al, na);
    }
    run_layer<HEADS, 0>(INC,  W1, a1_src, a1_dst, b1, B, nullptr);
    run_layer<HEADS, 0>(FMAX, W2, a2_src, a2_dst, b2, B, nullptr);
    run_layer<1, 1>    (FMAX, W3, a3_src, a3_dst, b3, B, (float*)d_out);
}

// round 10
// speedup vs baseline: 1.0823x; 1.0368x over previous
#include <cuda_runtime.h>
#include <cuda_bf16.h>
#include <math.h>
#include <stdint.h>

// Problem constants
#define NN     20000
#define EE     400000
#define ETOT   420000
#define INC    768
#define HID    128
#define HEADS  4
#define FMAX   512

// ---------------- device scratch ----------------
__device__ float g_hlin[(size_t)NN * FMAX];
__device__ float g_asrc[(size_t)NN * HEADS];
__device__ float g_adst[(size_t)NN * HEADS];
__device__ __nv_bfloat16 g_ah [(size_t)NN * INC];
__device__ __nv_bfloat16 g_al [(size_t)NN * INC];
__device__ __nv_bfloat16 g_wth[(size_t)FMAX * INC];
__device__ __nv_bfloat16 g_wtl[(size_t)FMAX * INC];
// CSR (built once per launch); esrc holds SOURCE node ids bucketed by dst
__device__ int g_deg[NN];
__device__ int g_cur[NN];
__device__ int g_rowptr[NN + 1];
__device__ int g_esrc[ETOT];

// ---------------- misc helpers ----------------
__device__ __forceinline__ int clampN(int v) { return v < 0 ? 0 : (v >= NN ? NN - 1 : v); }
__device__ __forceinline__ uint32_t smem_u32(const void* p) {
    uint32_t a;
    asm("{ .reg .u64 t; cvta.to.shared.u64 t, %1; cvt.u32.u64 %0, t; }" : "=r"(a) : "l"(p));
    return a;
}

__global__ void zero_int2_kernel(int* __restrict__ a, int* __restrict__ b, int n) {
    int i = blockIdx.x * blockDim.x + threadIdx.x;
    if (i < n) { a[i] = 0; b[i] = 0; }
}
__global__ void zero_f2_kernel(float* __restrict__ a, float* __restrict__ b, int n) {
    int i = blockIdx.x * blockDim.x + threadIdx.x;
    if (i < n) { a[i] = 0.f; b[i] = 0.f; }
}

// ---------------- CSR build ----------------
__global__ void count_kernel(const int* __restrict__ ei, int* __restrict__ deg) {
    int e = blockIdx.x * blockDim.x + threadIdx.x;
    if (e >= ETOT) return;
    int d = (e < EE) ? clampN(ei[EE + e]) : e - EE;
    atomicAdd(&deg[d], 1);
}

#define SCAN_T 1024
#define SCAN_CH 20
__global__ void scan_kernel(const int* __restrict__ deg, int* __restrict__ rowptr) {
    __shared__ int sums[SCAN_T];
    int t = threadIdx.x;
    int base = t * SCAN_CH;
    int local = 0;
#pragma unroll
    for (int i = 0; i < SCAN_CH; i++) {
        int idx = base + i;
        if (idx < NN) local += deg[idx];
    }
    sums[t] = local;
    __syncthreads();
    for (int off = 1; off < SCAN_T; off <<= 1) {
        int v = (t >= off) ? sums[t - off] : 0;
        __syncthreads();
        sums[t] += v;
        __syncthreads();
    }
    int run = sums[t] - local;
#pragma unroll
    for (int i = 0; i < SCAN_CH; i++) {
        int idx = base + i;
        if (idx < NN) { rowptr[idx] = run; run += deg[idx]; }
    }
    if (t == SCAN_T - 1) rowptr[NN] = sums[SCAN_T - 1];
}

__global__ void scatter_kernel(const int* __restrict__ ei,
                               const int* __restrict__ rowptr,
                               int* __restrict__ cur, int* __restrict__ esrc) {
    int e = blockIdx.x * blockDim.x + threadIdx.x;
    if (e >= ETOT) return;
    int s, d;
    if (e < EE) { s = clampN(ei[e]); d = clampN(ei[EE + e]); } else { s = d = e - EE; }
    int pos = rowptr[d] + atomicAdd(&cur[d], 1);
    esrc[pos] = s;
}

// ---------------- fp32 -> bf16 hi/lo split (x only) ----------------
__global__ void split_kernel(const float* __restrict__ x,
                             __nv_bfloat16* __restrict__ hi,
                             __nv_bfloat16* __restrict__ lo, int n) {
    int i = blockIdx.x * blockDim.x + threadIdx.x;
    if (i >= n) return;
    float v = x[i];
    __nv_bfloat16 h = __float2bfloat16(v);
    hi[i] = h;
    lo[i] = __float2bfloat16(v - __bfloat162float(h));
}

// W [K,N] fp32 -> Wt hi/lo [N,K] bf16 via smem-tiled transpose (both coalesced)
__global__ void splitT_kernel(const float* __restrict__ W,
                              __nv_bfloat16* __restrict__ hi,
                              __nv_bfloat16* __restrict__ lo, int K, int Nn) {
    __shared__ float t[32][33];
    const int tx = threadIdx.x;      // 0..31
    const int ty = threadIdx.y;      // 0..7
    const int n0 = blockIdx.x * 32;
    const int k0 = blockIdx.y * 32;
#pragma unroll
    for (int i = 0; i < 4; i++) {
        int k = k0 + ty + i * 8;
        t[ty + i * 8][tx] = W[(size_t)k * Nn + n0 + tx];
    }
    __syncthreads();
#pragma unroll
    for (int i = 0; i < 4; i++) {
        int n = n0 + ty + i * 8;
        float v = t[tx][ty + i * 8];
        __nv_bfloat16 h = __float2bfloat16(v);
        size_t o = (size_t)n * K + k0 + tx;
        hi[o] = h;
        lo[o] = __float2bfloat16(v - __bfloat162float(h));
    }
}

// ---------------- HMMA bf16 GEMM: 2-stage cp.async + ldmatrix -----------------
// C[M,N] = A[M,K] @ B^T; 3-product split Ah*Bh + Ah*Bl + Al*Bh.
// Fused epilogue: per-head attention dots asrc/adst += C . a_vec (each CTA's
// 128-col block == exactly one head).
#define SPAD 24
#define TILE_ELEMS (128 * SPAD)

__device__ __forceinline__ void mma_bf16(float* c, const uint32_t* a, const uint32_t* b) {
    asm volatile("mma.sync.aligned.m16n8k16.row.col.f32.bf16.bf16.f32 "
                 "{%0,%1,%2,%3}, {%4,%5,%6,%7}, {%8,%9}, {%0,%1,%2,%3};"
                 : "+f"(c[0]), "+f"(c[1]), "+f"(c[2]), "+f"(c[3])
                 : "r"(a[0]), "r"(a[1]), "r"(a[2]), "r"(a[3]),
                   "r"(b[0]), "r"(b[1]));
}
#define LDM_X4(r0, r1, r2, r3, a) \
    asm volatile("ldmatrix.sync.aligned.m8n8.x4.shared.b16 {%0,%1,%2,%3}, [%4];" \
                 : "=r"(r0), "=r"(r1), "=r"(r2), "=r"(r3) : "r"(a))
#define CP_ASYNC16(dst, src) \
    asm volatile("cp.async.ca.shared.global [%0], [%1], 16;" :: "r"(dst), "l"(src))

template <int H>
__global__ void __launch_bounds__(256)
hgemm_kernel(const __nv_bfloat16* __restrict__ Ah,
             const __nv_bfloat16* __restrict__ Al,
             const __nv_bfloat16* __restrict__ Bh,
             const __nv_bfloat16* __restrict__ Bl,
             float* __restrict__ C,
             const float* __restrict__ avec_src,   // [H*HID] flat
             const float* __restrict__ avec_dst,
             float* __restrict__ asrc,             // [NN*H]
             float* __restrict__ adst,
             int M, int K, int Nn) {
    __shared__ __nv_bfloat16 sm[2 * 4 * TILE_ELEMS];   // 48KB

    const int tid  = threadIdx.x;
    const int lane = tid & 31;
    const int wid  = tid >> 5;
    const int wm   = (wid >> 2) * 64;
    const int wn   = (wid & 3) * 32;
    const int row0 = blockIdx.y * 128;
    const int col0 = blockIdx.x * 128;
    const int g4   = lane >> 2;
    const int t4   = lane & 3;

    const int a_off = (lane & 15) * SPAD + (lane >> 4) * 8;
    const int b_off = ((lane & 7) + ((lane & 16) ? 8 : 0)) * SPAD + ((lane & 8) ? 8 : 0);

    const int lr = tid >> 1;
    const int lc = (tid & 1) * 8;

    float acc[4][4][4];
#pragma unroll
    for (int a = 0; a < 4; a++)
#pragma unroll
        for (int b = 0; b < 4; b++)
#pragma unroll
            for (int c = 0; c < 4; c++) acc[a][b][c] = 0.f;

    const int nCh = K >> 4;
    const int gra = min(row0 + lr, M - 1);
    const int grb = col0 + lr;

#define ISSUE(ch) do {                                                          \
    __nv_bfloat16* sb_ = sm + ((ch) & 1) * 4 * TILE_ELEMS;                      \
    int kc0_ = (ch) << 4;                                                       \
    uint32_t d0 = smem_u32(sb_ + 0 * TILE_ELEMS + lr * SPAD + lc);              \
    uint32_t d1 = smem_u32(sb_ + 1 * TILE_ELEMS + lr * SPAD + lc);              \
    uint32_t d2 = smem_u32(sb_ + 2 * TILE_ELEMS + lr * SPAD + lc);              \
    uint32_t d3 = smem_u32(sb_ + 3 * TILE_ELEMS + lr * SPAD + lc);              \
    CP_ASYNC16(d0, Ah + (size_t)gra * K + kc0_ + lc);                           \
    CP_ASYNC16(d1, Al + (size_t)gra * K + kc0_ + lc);                           \
    CP_ASYNC16(d2, Bh + (size_t)grb * K + kc0_ + lc);                           \
    CP_ASYNC16(d3, Bl + (size_t)grb * K + kc0_ + lc);                           \
    asm volatile("cp.async.commit_group;");                                     \
} while (0)

    ISSUE(0);
    for (int ch = 0; ch < nCh; ch++) {
        if (ch + 1 < nCh) {
            ISSUE(ch + 1);
            asm volatile("cp.async.wait_group 1;");
        } else {
            asm volatile("cp.async.wait_group 0;");
        }
        __syncthreads();

        const __nv_bfloat16* sb = sm + (ch & 1) * 4 * TILE_ELEMS;
        const uint32_t bAh = smem_u32(sb);
        const uint32_t bAl = bAh + TILE_ELEMS * 2;
        const uint32_t bBh = bAl + TILE_ELEMS * 2;
        const uint32_t bBl = bBh + TILE_ELEMS * 2;

        uint32_t bh[4][2], bl[4][2];
#pragma unroll
        for (int ntp = 0; ntp < 2; ntp++) {
            uint32_t off = (uint32_t)((wn + ntp * 16) * SPAD + b_off) * 2;
            LDM_X4(bh[2 * ntp][0], bh[2 * ntp][1], bh[2 * ntp + 1][0], bh[2 * ntp + 1][1], bBh + off);
            LDM_X4(bl[2 * ntp][0], bl[2 * ntp][1], bl[2 * ntp + 1][0], bl[2 * ntp + 1][1], bBl + off);
        }
#pragma unroll
        for (int mt = 0; mt < 4; mt++) {
            uint32_t off = (uint32_t)((wm + mt * 16) * SPAD + a_off) * 2;
            uint32_t ah[4], al[4];
            LDM_X4(ah[0], ah[1], ah[2], ah[3], bAh + off);
            LDM_X4(al[0], al[1], al[2], al[3], bAl + off);
#pragma unroll
            for (int nt = 0; nt < 4; nt++) {
                mma_bf16(acc[mt][nt], ah, bh[nt]);
                mma_bf16(acc[mt][nt], ah, bl[nt]);
                mma_bf16(acc[mt][nt], al, bh[nt]);
            }
        }
        __syncthreads();
    }
#undef ISSUE

    // ---- epilogue: store C + fused attention dots ----
    const int h = col0 >> 7;   // this CTA's head
    // attention vector values for this thread's 8 columns
    float vs[4][2], vd[4][2];
#pragma unroll
    for (int nt = 0; nt < 4; nt++) {
        int gc = col0 + wn + nt * 8 + t4 * 2;
#pragma unroll
        for (int j = 0; j < 2; j++) {
            vs[nt][j] = avec_src[gc + j];
            vd[nt][j] = avec_dst[gc + j];
        }
    }

#pragma unroll
    for (int mt = 0; mt < 4; mt++) {
        float ps0 = 0.f, pd0 = 0.f, ps1 = 0.f, pd1 = 0.f;
#pragma unroll
        for (int nt = 0; nt < 4; nt++) {
            int gm = row0 + wm + mt * 16 + g4;
            int gc = col0 + wn + nt * 8 + t4 * 2;
            if (gm < M)
                *(float2*)&C[(size_t)gm * Nn + gc] = make_float2(acc[mt][nt][0], acc[mt][nt][1]);
            if (gm + 8 < M)
                *(float2*)&C[(size_t)(gm + 8) * Nn + gc] = make_float2(acc[mt][nt][2], acc[mt][nt][3]);
            ps0 = fmaf(acc[mt][nt][0], vs[nt][0], fmaf(acc[mt][nt][1], vs[nt][1], ps0));
            pd0 = fmaf(acc[mt][nt][0], vd[nt][0], fmaf(acc[mt][nt][1], vd[nt][1], pd0));
            ps1 = fmaf(acc[mt][nt][2], vs[nt][0], fmaf(acc[mt][nt][3], vs[nt][1], ps1));
            pd1 = fmaf(acc[mt][nt][2], vd[nt][0], fmaf(acc[mt][nt][3], vd[nt][1], pd1));
        }
        // quad reduce over t4 (lanes differing in bits 0,1)
#pragma unroll
        for (int o = 1; o <= 2; o <<= 1) {
            ps0 += __shfl_xor_sync(0xffffffffu, ps0, o);
            pd0 += __shfl_xor_sync(0xffffffffu, pd0, o);
            ps1 += __shfl_xor_sync(0xffffffffu, ps1, o);
            pd1 += __shfl_xor_sync(0xffffffffu, pd1, o);
        }
        if (t4 == 0) {
            int gm = row0 + wm + mt * 16 + g4;
            if (gm < M) {
                atomicAdd(&asrc[(size_t)gm * H + h], ps0);
                atomicAdd(&adst[(size_t)gm * H + h], pd0);
            }
            if (gm + 8 < M) {
                atomicAdd(&asrc[(size_t)(gm + 8) * H + h], ps1);
                atomicAdd(&adst[(size_t)(gm + 8) * H + h], pd1);
            }
        }
    }
}

// ---------------- fused aggregate (4x unrolled gather) ----------------------
template <int H, int MODE>
__global__ void aggregate_kernel(const int* __restrict__ rowptr,
                                 const int* __restrict__ esrc,
                                 const float* __restrict__ asrc,
                                 const float* __restrict__ adst,
                                 const float* __restrict__ hlin,
                                 const float* __restrict__ bias,
                                 __nv_bfloat16* __restrict__ hi,
                                 __nv_bfloat16* __restrict__ lo,
                                 float* __restrict__ out) {
    int gw = (blockIdx.x * blockDim.x + threadIdx.x) >> 5;
    int lane = threadIdx.x & 31;
    if (gw >= NN * H) return;
    int n = gw / H, h = gw - n * H;
    float adst_nh = adst[gw];
    int beg = rowptr[n], end = rowptr[n + 1];

    float4 acc = make_float4(0.f, 0.f, 0.f, 0.f);
    float ssum = 0.f;

    for (int base = beg; base < end; base += 32) {
        int j = base + lane;
        float vj = 0.f;
        int sj = 0;
        if (j < end) {
            sj = esrc[j];
            float v = asrc[(size_t)sj * H + h] + adst_nh;
            v = (v > 0.f) ? v : 0.2f * v;
            vj = __expf(v);
        }
        int cnt = min(32, end - base);
        int t = 0;
        for (; t + 4 <= cnt; t += 4) {
            float v0 = __shfl_sync(0xffffffffu, vj, t);
            float v1 = __shfl_sync(0xffffffffu, vj, t + 1);
            float v2 = __shfl_sync(0xffffffffu, vj, t + 2);
            float v3 = __shfl_sync(0xffffffffu, vj, t + 3);
            int s0 = __shfl_sync(0xffffffffu, sj, t);
            int s1 = __shfl_sync(0xffffffffu, sj, t + 1);
            int s2 = __shfl_sync(0xffffffffu, sj, t + 2);
            int s3 = __shfl_sync(0xffffffffu, sj, t + 3);
            float4 h0 = ((const float4*)(hlin + ((size_t)s0 * H + h) * HID))[lane];
            float4 h1 = ((const float4*)(hlin + ((size_t)s1 * H + h) * HID))[lane];
            float4 h2 = ((const float4*)(hlin + ((size_t)s2 * H + h) * HID))[lane];
            float4 h3 = ((const float4*)(hlin + ((size_t)s3 * H + h) * HID))[lane];
            acc.x = fmaf(v0, h0.x, acc.x); acc.y = fmaf(v0, h0.y, acc.y);
            acc.z = fmaf(v0, h0.z, acc.z); acc.w = fmaf(v0, h0.w, acc.w);
            acc.x = fmaf(v1, h1.x, acc.x); acc.y = fmaf(v1, h1.y, acc.y);
            acc.z = fmaf(v1, h1.z, acc.z); acc.w = fmaf(v1, h1.w, acc.w);
            acc.x = fmaf(v2, h2.x, acc.x); acc.y = fmaf(v2, h2.y, acc.y);
            acc.z = fmaf(v2, h2.z, acc.z); acc.w = fmaf(v2, h2.w, acc.w);
            acc.x = fmaf(v3, h3.x, acc.x); acc.y = fmaf(v3, h3.y, acc.y);
            acc.z = fmaf(v3, h3.z, acc.z); acc.w = fmaf(v3, h3.w, acc.w);
            ssum += (v0 + v1) + (v2 + v3);
        }
        for (; t < cnt; t++) {
            float v = __shfl_sync(0xffffffffu, vj, t);
            int s   = __shfl_sync(0xffffffffu, sj, t);
            float4 hv = ((const float4*)(hlin + ((size_t)s * H + h) * HID))[lane];
            acc.x = fmaf(v, hv.x, acc.x);
            acc.y = fmaf(v, hv.y, acc.y);
            acc.z = fmaf(v, hv.z, acc.z);
            acc.w = fmaf(v, hv.w, acc.w);
            ssum += v;
        }
    }
    float inv = 1.f / (ssum + 1e-16f);
    int f = h * HID + lane * 4;
    float4 bv = *(const float4*)(bias + f);
    float4 o;
    o.x = acc.x * inv + bv.x;
    o.y = acc.y * inv + bv.y;
    o.z = acc.z * inv + bv.z;
    o.w = acc.w * inv + bv.w;
    if (MODE == 0) {
        o.x = (o.x > 0.f) ? o.x : expm1f(o.x);
        o.y = (o.y > 0.f) ? o.y : expm1f(o.y);
        o.z = (o.z > 0.f) ? o.z : expm1f(o.z);
        o.w = (o.w > 0.f) ? o.w : expm1f(o.w);
        size_t off = (size_t)gw * HID + lane * 4;
        __nv_bfloat16 hx = __float2bfloat16(o.x);
        __nv_bfloat16 hy = __float2bfloat16(o.y);
        __nv_bfloat16 hz = __float2bfloat16(o.z);
        __nv_bfloat16 hw = __float2bfloat16(o.w);
        hi[off + 0] = hx;  lo[off + 0] = __float2bfloat16(o.x - __bfloat162float(hx));
        hi[off + 1] = hy;  lo[off + 1] = __float2bfloat16(o.y - __bfloat162float(hy));
        hi[off + 2] = hz;  lo[off + 2] = __float2bfloat16(o.z - __bfloat162float(hz));
        hi[off + 3] = hw;  lo[off + 3] = __float2bfloat16(o.w - __bfloat162float(hw));
    } else {
        *(float4*)&out[(size_t)n * HID + lane * 4] = o;
    }
}

// ---------------- host orchestration ----------------
struct Buffers {
    float *hlin, *asrc, *adst;
    __nv_bfloat16 *ah, *al, *wth, *wtl;
    int *deg, *cur, *rowptr, *esrc;
};

template <int H, int MODE>
static void run_layer(int K, const float* W, const float* a_src, const float* a_dst,
                      const float* bias, const Buffers& B, float* out_fp32) {
    const int F = H * HID;
    {
        dim3 grid(F / 32, K / 32);
        splitT_kernel<<<grid, dim3(32, 8)>>>(W, B.wth, B.wtl, K, F);
        int nh = NN * H;
        zero_f2_kernel<<<(nh + 255) / 256, 256>>>(B.asrc, B.adst, nh);
    }
    {
        dim3 grid(F / 128, (NN + 127) / 128);
        hgemm_kernel<H><<<grid, 256>>>(B.ah, B.al, B.wth, B.wtl, B.hlin,
                                       a_src, a_dst, B.asrc, B.adst, NN, K, F);
    }
    {
        int warps = NN * H;
        aggregate_kernel<H, MODE><<<(warps * 32 + 255) / 256, 256>>>(
            B.rowptr, B.esrc, B.asrc, B.adst, B.hlin, bias, B.ah, B.al, out_fp32);
    }
}

extern "C" void kernel_launch(void* const* d_in, const int* in_sizes, int n_in,
                              void* d_out, int out_size) {
    const float* x       = (const float*)d_in[0];
    const int*   ei      = (const int*)d_in[1];
    const float* W1      = (const float*)d_in[2];
    const float* a1_src  = (const float*)d_in[3];
    const float* a1_dst  = (const float*)d_in[4];
    const float* b1      = (const float*)d_in[5];
    const float* W2      = (const float*)d_in[6];
    const float* a2_src  = (const float*)d_in[7];
    const float* a2_dst  = (const float*)d_in[8];
    const float* b2      = (const float*)d_in[9];
    const float* W3      = (const float*)d_in[10];
    const float* a3_src  = (const float*)d_in[11];
    const float* a3_dst  = (const float*)d_in[12];
    const float* b3      = (const float*)d_in[13];

    Buffers B;
    cudaGetSymbolAddress((void**)&B.hlin,   g_hlin);
    cudaGetSymbolAddress((void**)&B.asrc,   g_asrc);
    cudaGetSymbolAddress((void**)&B.adst,   g_adst);
    cudaGetSymbolAddress((void**)&B.ah,     g_ah);
    cudaGetSymbolAddress((void**)&B.al,     g_al);
    cudaGetSymbolAddress((void**)&B.wth,    g_wth);
    cudaGetSymbolAddress((void**)&B.wtl,    g_wtl);
    cudaGetSymbolAddress((void**)&B.deg,    g_deg);
    cudaGetSymbolAddress((void**)&B.cur,    g_cur);
    cudaGetSymbolAddress((void**)&B.rowptr, g_rowptr);
    cudaGetSymbolAddress((void**)&B.esrc,   g_esrc);

    // CSR build (once; reused by all 3 layers)
    zero_int2_kernel<<<(NN + 255) / 256, 256>>>(B.deg, B.cur, NN);
    count_kernel<<<(ETOT + 255) / 256, 256>>>(ei, B.deg);
    scan_kernel<<<1, SCAN_T>>>(B.deg, B.rowptr);
    scatter_kernel<<<(ETOT + 255) / 256, 256>>>(ei, B.rowptr, B.cur, B.esrc);

    // split x into bf16 hi/lo (layer-1 GEMM input)
    {
        int na = NN * INC;
        split_kernel<<<(na + 255) / 256, 256>>>(x, B.ah, B.al, na);
    }
    run_layer<HEADS, 0>(INC,  W1, a1_src, a1_dst, b1, B, nullptr);
    run_layer<HEADS, 0>(FMAX, W2, a2_src, a2_dst, b2, B, nullptr);
    run_layer<1, 1>    (FMAX, W3, a3_src, a3_dst, b3, B, (float*)d_out);
}